// round 5
// baseline (speedup 1.0000x reference)
#include <cuda_runtime.h>

// LinearActorNet: B=2048, K=512, N=256, T=64. task_id/action int32.
// out layout (float32): [action(B) | log_prob(B) | entropy(B)]
//
// Two-kernel pipeline:
//  1) setup: one-CTA ballot counting-sort of sample indices by task -> globals
//  2) gemm+softmax: grid (64 tasks x 16 tile-slots), 256 thr, TM=8 rows,
//     1 output column per thread, packed f32x2 FFMA, fused log-softmax.

#define BB 2048
#define KK 512
#define NN 256
#define TT 64
#define TM 8
#define NT 256
#define NSLOT 16

__device__ unsigned short g_list[BB];
__device__ int g_cnt[TT];
__device__ int g_off[TT];

union f2u { float2 f; unsigned long long u; };
__device__ __forceinline__ unsigned long long pk(float lo, float hi) {
    f2u u; u.f = make_float2(lo, hi); return u.u;
}
__device__ __forceinline__ float fold(unsigned long long v) {
    f2u u; u.u = v; return u.f.x + u.f.y;
}
#define FFMA2(d, a, b) \
    asm("fma.rn.f32x2 %0, %1, %2, %0;" : "+l"(d) : "l"(a), "l"(b))

// ---------------- setup: counting sort by task ----------------
__global__ __launch_bounds__(1024, 1)
void setup_kernel(const int* __restrict__ task_id)
{
    __shared__ int s_cnt[TT];
    __shared__ int s_off[TT];
    const int wid  = threadIdx.x >> 5;
    const int lane = threadIdx.x & 31;
    const unsigned lt = (1u << lane) - 1u;

    // counts: warp w handles tasks w and w+32
    for (int t = wid; t < TT; t += 32) {
        int c = 0;
        for (int chunk = 0; chunk < BB / 32; chunk++) {
            int id = task_id[chunk * 32 + lane];
            c += __popc(__ballot_sync(0xffffffffu, id == t));
        }
        if (lane == 0) s_cnt[t] = c;
    }
    __syncthreads();
    if (threadIdx.x == 0) {
        int a = 0;
        for (int t = 0; t < TT; t++) { s_off[t] = a; a += s_cnt[t]; }
    }
    __syncthreads();
    // scatter (order deterministic: ascending sample index within task)
    for (int t = wid; t < TT; t += 32) {
        int base = s_off[t];
        for (int chunk = 0; chunk < BB / 32; chunk++) {
            int idx = chunk * 32 + lane;
            int id  = task_id[idx];
            unsigned m = __ballot_sync(0xffffffffu, id == t);
            if (id == t) g_list[base + __popc(m & lt)] = (unsigned short)idx;
            base += __popc(m);
        }
    }
    if (threadIdx.x < TT) {
        g_cnt[threadIdx.x] = s_cnt[threadIdx.x];
        g_off[threadIdx.x] = s_off[threadIdx.x];
    }
}

// ---------------- gemm + fused log-softmax ----------------
__global__ __launch_bounds__(NT, 2)
void actor_kernel(const float* __restrict__ xs,
                  const int* __restrict__ action,
                  const float* __restrict__ W,
                  const float* __restrict__ bias,
                  float* __restrict__ out)
{
    __shared__ float xs_s[TM][KK];          // 16 KB
    __shared__ float redm[TM][8];
    __shared__ float reda[TM][8];
    __shared__ float redb[TM][8];

    const int tid  = threadIdx.x;           // output column n = tid
    const int t    = blockIdx.x;
    const int slot = blockIdx.y;
    const int lane = tid & 31;
    const int wid  = tid >> 5;

    const int cnt = g_cnt[t];
    if (slot * TM >= cnt) return;
    const int off = g_off[t];

    const float* __restrict__ Wt = W + (size_t)t * (KK * NN) + tid;
    const float  bv = bias[t * NN + tid];

    for (int tile = slot; tile * TM < cnt; tile += NSLOT) {
        const int m0 = tile * TM;
        const int mc = min(TM, cnt - m0);
        __syncthreads();

        // ---- stage xs tile [TM][KK] (float4, coalesced) ----
        #pragma unroll
        for (int i = 0; i < (TM * KK / 4) / NT; i++) {   // 4 iters
            int idx = i * NT + tid;
            int m = idx >> 7;
            int c = idx & 127;
            float4 v = make_float4(0.f, 0.f, 0.f, 0.f);
            if (m < mc) {
                const float4* src =
                    (const float4*)(xs + (size_t)g_list[off + m0 + m] * KK);
                v = src[c];
            }
            *(float4*)&xs_s[m][c * 4] = v;
        }
        __syncthreads();

        // ---- GEMM: acc[m] (packed f32x2) over k ----
        unsigned long long acc[TM];
        #pragma unroll
        for (int m = 0; m < TM; m++) acc[m] = 0ull;

        #pragma unroll 4
        for (int k = 0; k < KK; k += 4) {
            const float* wk = Wt + k * NN;
            float w0 = wk[0], w1 = wk[NN], w2 = wk[2 * NN], w3 = wk[3 * NN];
            unsigned long long wp0 = pk(w0, w1), wp1 = pk(w2, w3);
            #pragma unroll
            for (int m = 0; m < TM; m++) {
                ulonglong2 xv = *(const ulonglong2*)&xs_s[m][k];  // LDS.128 bcast
                FFMA2(acc[m], xv.x, wp0);
                FFMA2(acc[m], xv.y, wp1);
            }
        }

        float v[TM];
        #pragma unroll
        for (int m = 0; m < TM; m++) v[m] = fold(acc[m]) + bv;

        // ---- block max per row (256 cols across 8 warps) ----
        float mx[TM];
        #pragma unroll
        for (int m = 0; m < TM; m++) {
            float x = v[m];
            #pragma unroll
            for (int o = 16; o > 0; o >>= 1)
                x = fmaxf(x, __shfl_xor_sync(0xffffffffu, x, o));
            if (lane == 0) redm[m][wid] = x;
        }
        __syncthreads();
        #pragma unroll
        for (int m = 0; m < TM; m++) {
            float x = redm[m][0];
            #pragma unroll
            for (int w = 1; w < 8; w++) x = fmaxf(x, redm[m][w]);
            mx[m] = x;
        }

        // ---- block sums: s1 = sum exp(d), s2 = sum exp(d)*d ----
        #pragma unroll
        for (int m = 0; m < TM; m++) {
            float d = v[m] - mx[m];
            float e = __expf(d);
            float s1 = e, s2 = e * d;
            #pragma unroll
            for (int o = 16; o > 0; o >>= 1) {
                s1 += __shfl_xor_sync(0xffffffffu, s1, o);
                s2 += __shfl_xor_sync(0xffffffffu, s2, o);
            }
            if (lane == 0) { reda[m][wid] = s1; redb[m][wid] = s2; }
        }
        __syncthreads();

        // ---- outputs ----
        #pragma unroll
        for (int m = 0; m < TM; m++) {
            if (m >= mc) break;
            float s1 = 0.f, s2 = 0.f;
            #pragma unroll
            for (int w = 0; w < 8; w++) { s1 += reda[m][w]; s2 += redb[m][w]; }
            const int   gb   = g_list[off + m0 + m];
            const int   a    = action[gb];
            const float logS = logf(s1);
            if (tid == a)
                out[BB + gb] = v[m] - mx[m] - logS;        // log_prob
            if (tid == 0) {
                out[gb]          = (float)a;               // action (as float)
                out[2 * BB + gb] = logS - s2 / s1;         // entropy
            }
        }
    }
}

extern "C" void kernel_launch(void* const* d_in, const int* in_sizes, int n_in,
                              void* d_out, int out_size) {
    const float* xs      = (const float*)d_in[0];
    const int*   task_id = (const int*)d_in[1];
    const int*   action  = (const int*)d_in[2];
    const float* W       = (const float*)d_in[3];
    const float* bias    = (const float*)d_in[4];
    float*       out     = (float*)d_out;

    setup_kernel<<<1, 1024>>>(task_id);
    dim3 grid(TT, NSLOT);
    actor_kernel<<<grid, NT>>>(xs, action, W, bias, out);
}

// round 6
// speedup vs baseline: 1.4599x; 1.4599x over previous
#include <cuda_runtime.h>

// LinearActorNet: B=2048, K=512, N=256, T=64. task_id/action int32.
// out layout (float32): [action(B) | log_prob(B) | entropy(B)]
//
// Two-kernel pipeline:
//  1) setup: 64 CTAs (one per task), ballot compaction into fixed-stride
//     per-task segments (no global prefix sum).
//  2) actor: grid (64 tasks x 16 tile-slots), 128 thr, TM=8 rows,
//     2 output columns per thread, packed f32x2 FFMA, fused log-softmax.

#define BB 2048
#define KK 512
#define NN 256
#define TT 64
#define TM 8
#define NT 128
#define NSLOT 16
#define LSTRIDE 128

__device__ unsigned short g_list[TT * LSTRIDE];
__device__ int g_cnt[TT];

union f2u { float2 f; unsigned long long u; };
__device__ __forceinline__ unsigned long long pk(float lo, float hi) {
    f2u u; u.f = make_float2(lo, hi); return u.u;
}
__device__ __forceinline__ float fold(unsigned long long v) {
    f2u u; u.u = v; return u.f.x + u.f.y;
}
#define FFMA2(d, a, b) \
    asm("fma.rn.f32x2 %0, %1, %2, %0;" : "+l"(d) : "l"(a), "l"(b))

// ---------------- setup: per-task parallel compaction ----------------
__global__ __launch_bounds__(128, 8)
void setup_kernel(const int* __restrict__ task_id)
{
    const int t    = blockIdx.x;
    const int lane = threadIdx.x & 31;
    const int w    = threadIdx.x >> 5;          // 0..3
    const unsigned lt = (1u << lane) - 1u;
    __shared__ int wcnt[4];

    // pass 1: per-warp counts (warp w covers samples [w*512, (w+1)*512))
    int c = 0;
    #pragma unroll
    for (int i = 0; i < 16; i++) {
        int idx = w * 512 + i * 32 + lane;
        c += __popc(__ballot_sync(0xffffffffu, task_id[idx] == t));
    }
    if (lane == 0) wcnt[w] = c;
    __syncthreads();
    int base = 0;
    #pragma unroll
    for (int i = 0; i < 4; i++) if (i < w) base += wcnt[i];
    if (w == 3 && lane == 0) g_cnt[t] = base + wcnt[3];

    // pass 2: scatter (ascending sample index within task)
    #pragma unroll
    for (int i = 0; i < 16; i++) {
        int idx = w * 512 + i * 32 + lane;
        bool p = (task_id[idx] == t);
        unsigned m = __ballot_sync(0xffffffffu, p);
        if (p) {
            int pos = base + __popc(m & lt);
            if (pos < LSTRIDE)
                g_list[t * LSTRIDE + pos] = (unsigned short)idx;
        }
        base += __popc(m);
    }
}

// ---------------- gemm + fused log-softmax ----------------
__global__ __launch_bounds__(NT, 4)
void actor_kernel(const float* __restrict__ xs,
                  const int* __restrict__ action,
                  const float* __restrict__ W,
                  const float* __restrict__ bias,
                  float* __restrict__ out)
{
    __shared__ float xs_s[TM][KK];          // 16 KB
    __shared__ float redm[TM][4];
    __shared__ float reda[TM][4];
    __shared__ float redb[TM][4];

    const int tid  = threadIdx.x;           // owns cols tid and tid+128
    const int t    = blockIdx.x;
    const int slot = blockIdx.y;
    const int lane = tid & 31;
    const int wid  = tid >> 5;

    const int cnt = min(g_cnt[t], LSTRIDE);
    if (slot * TM >= cnt) return;
    const unsigned short* __restrict__ lst = g_list + t * LSTRIDE;

    const float* __restrict__ Wt = W + (size_t)t * (KK * NN) + tid;
    const float bv0 = bias[t * NN + tid];
    const float bv1 = bias[t * NN + tid + 128];

    for (int tile = slot; tile * TM < cnt; tile += NSLOT) {
        const int m0 = tile * TM;
        const int mc = min(TM, cnt - m0);
        __syncthreads();

        // ---- stage xs tile [TM][KK] (float4, coalesced) ----
        #pragma unroll
        for (int i = 0; i < (TM * KK / 4) / NT; i++) {   // 8 iters
            int idx = i * NT + tid;
            int m = idx >> 7;
            int c = idx & 127;
            float4 v = make_float4(0.f, 0.f, 0.f, 0.f);
            if (m < mc) {
                const float4* src =
                    (const float4*)(xs + (size_t)lst[m0 + m] * KK);
                v = src[c];
            }
            *(float4*)&xs_s[m][c * 4] = v;
        }
        __syncthreads();

        // ---- GEMM: 2 cols/thread, packed f32x2 accumulators ----
        unsigned long long acc0[TM], acc1[TM];
        #pragma unroll
        for (int m = 0; m < TM; m++) { acc0[m] = 0ull; acc1[m] = 0ull; }

        #pragma unroll 2
        for (int k = 0; k < KK; k += 4) {
            const float* wk = Wt + k * NN;
            float a0 = wk[0],   a1 = wk[NN],     a2 = wk[2*NN],     a3 = wk[3*NN];
            float b0 = wk[128], b1 = wk[NN+128], b2 = wk[2*NN+128], b3 = wk[3*NN+128];
            unsigned long long wA0 = pk(a0, a1), wA1 = pk(a2, a3);
            unsigned long long wB0 = pk(b0, b1), wB1 = pk(b2, b3);
            #pragma unroll
            for (int m = 0; m < TM; m++) {
                ulonglong2 xv = *(const ulonglong2*)&xs_s[m][k];  // LDS.128 bcast
                FFMA2(acc0[m], xv.x, wA0);
                FFMA2(acc0[m], xv.y, wA1);
                FFMA2(acc1[m], xv.x, wB0);
                FFMA2(acc1[m], xv.y, wB1);
            }
        }

        float v0[TM], v1[TM];
        #pragma unroll
        for (int m = 0; m < TM; m++) {
            v0[m] = fold(acc0[m]) + bv0;
            v1[m] = fold(acc1[m]) + bv1;
        }

        // ---- block max per row (4 warps) ----
        float mx[TM];
        #pragma unroll
        for (int m = 0; m < TM; m++) {
            float x = fmaxf(v0[m], v1[m]);
            #pragma unroll
            for (int o = 16; o > 0; o >>= 1)
                x = fmaxf(x, __shfl_xor_sync(0xffffffffu, x, o));
            if (lane == 0) redm[m][wid] = x;
        }
        __syncthreads();
        #pragma unroll
        for (int m = 0; m < TM; m++)
            mx[m] = fmaxf(fmaxf(redm[m][0], redm[m][1]),
                          fmaxf(redm[m][2], redm[m][3]));

        // ---- block sums: s1 = sum exp(d), s2 = sum exp(d)*d ----
        #pragma unroll
        for (int m = 0; m < TM; m++) {
            float d0 = v0[m] - mx[m];
            float d1 = v1[m] - mx[m];
            float e0 = __expf(d0), e1 = __expf(d1);
            float s1 = e0 + e1;
            float s2 = e0 * d0 + e1 * d1;
            #pragma unroll
            for (int o = 16; o > 0; o >>= 1) {
                s1 += __shfl_xor_sync(0xffffffffu, s1, o);
                s2 += __shfl_xor_sync(0xffffffffu, s2, o);
            }
            if (lane == 0) { reda[m][wid] = s1; redb[m][wid] = s2; }
        }
        __syncthreads();

        // ---- outputs ----
        #pragma unroll
        for (int m = 0; m < TM; m++) {
            if (m >= mc) break;
            float s1 = reda[m][0] + reda[m][1] + reda[m][2] + reda[m][3];
            float s2 = redb[m][0] + redb[m][1] + redb[m][2] + redb[m][3];
            const int   gb   = lst[m0 + m];
            const int   a    = action[gb];
            const float logS = logf(s1);
            if (tid == (a & 127)) {
                float chosen = (a < 128) ? v0[m] : v1[m];
                out[BB + gb] = chosen - mx[m] - logS;      // log_prob
            }
            if (tid == 0) {
                out[gb]          = (float)a;               // action (as float)
                out[2 * BB + gb] = logS - s2 / s1;         // entropy
            }
        }
    }
}

extern "C" void kernel_launch(void* const* d_in, const int* in_sizes, int n_in,
                              void* d_out, int out_size) {
    const float* xs      = (const float*)d_in[0];
    const int*   task_id = (const int*)d_in[1];
    const int*   action  = (const int*)d_in[2];
    const float* W       = (const float*)d_in[3];
    const float* bias    = (const float*)d_in[4];
    float*       out     = (float*)d_out;

    setup_kernel<<<TT, 128>>>(task_id);
    dim3 grid(TT, NSLOT);
    actor_kernel<<<grid, NT>>>(xs, action, W, bias, out);
}